// round 9
// baseline (speedup 1.0000x reference)
#include <cuda_runtime.h>
#include <cuda_bf16.h>
#include <cstdint>

#define NN 50000
#define NE 800000
#define NF 500
#define NH 256
#define NC 10
#define HID2 512   // both networks' hidden concatenated
#define KPAD 512   // padded K for tensor-core GEMM

// ---------------- scratch (device globals; no runtime allocation) -----------
__device__ __align__(256) float g_H0[NN * HID2];   // x@W1 + b1 (both nets)
__device__ __align__(256) float g_H2[NN * 2 * NC]; // relu(spmm(H0)) @ W2 + b2
__device__ __align__(256) __nv_bfloat16 g_A0[NN * KPAD];   // hi(x), K-padded
__device__ __align__(256) __nv_bfloat16 g_A1[NN * KPAD];   // lo(x)
__device__ __align__(256) __nv_bfloat16 g_B0[HID2 * KPAD]; // hi(W^T) [n][k]
__device__ __align__(256) __nv_bfloat16 g_B1[HID2 * KPAD]; // lo(W^T)
__device__ __align__(256) float g_bias[HID2];
__device__ int   g_rowptr[NN + 1];
__device__ int   g_cnt[NN];
__device__ int   g_fill[NN];
__device__ int   g_btot[256];
__device__ int   g_cols[NE];
__device__ float g_w[NE];
__device__ int   g_is64;

// ================= helpers ===================================================
__device__ __forceinline__ uint32_t smem_u32(const void* p) {
    uint32_t a;
    asm("{ .reg .u64 t; cvta.to.shared.u64 t, %1; cvt.u32.u64 %0, t; }"
        : "=r"(a) : "l"(p));
    return a;
}
#define SMEM_SWIZZLE_128B(off) ((off) ^ (((off) >> 3) & 0x70))

__device__ __forceinline__ void ldsm_x4(uint32_t* d, uint32_t addr) {
    asm volatile("ldmatrix.sync.aligned.m8n8.x4.shared.b16 {%0,%1,%2,%3}, [%4];"
                 : "=r"(d[0]), "=r"(d[1]), "=r"(d[2]), "=r"(d[3]) : "r"(addr));
}
__device__ __forceinline__ void mma16816(float* c, const uint32_t* a,
                                         uint32_t b0, uint32_t b1) {
    asm volatile("mma.sync.aligned.m16n8k16.row.col.f32.bf16.bf16.f32 "
                 "{%0,%1,%2,%3}, {%4,%5,%6,%7}, {%8,%9}, {%0,%1,%2,%3};"
                 : "+f"(c[0]), "+f"(c[1]), "+f"(c[2]), "+f"(c[3])
                 : "r"(a[0]), "r"(a[1]), "r"(a[2]), "r"(a[3]), "r"(b0), "r"(b1));
}
__device__ __forceinline__ void cp_async16(uint32_t dst, const void* src, int src_sz) {
    asm volatile("cp.async.cg.shared.global [%0], [%1], 16, %2;"
                 :: "r"(dst), "l"(src), "r"(src_sz) : "memory");
}
#define CP_COMMIT() asm volatile("cp.async.commit_group;" ::: "memory")
#define CP_WAIT1()  asm volatile("cp.async.wait_group 1;" ::: "memory")
#define CP_WAIT0()  asm volatile("cp.async.wait_group 0;" ::: "memory")

// ---------------- dtype detect + CSR build ----------------------------------
__global__ void zero_kernel() {
    int i = blockIdx.x * blockDim.x + threadIdx.x;
    if (i < NN) { g_cnt[i] = 0; g_fill[i] = 0; }
    if (i == 0) g_is64 = 1;
}

// init H2 to the biases (chunked spmm1 accumulates partials on top)
__global__ void initH2_kernel(const float* __restrict__ b2a,
                              const float* __restrict__ b2b) {
    int i = blockIdx.x * blockDim.x + threadIdx.x;
    if (i >= NN * 2 * NC) return;
    int c = i % (2 * NC);
    g_H2[i] = (c < NC) ? __ldg(&b2a[c]) : __ldg(&b2b[c - NC]);
}

__global__ void detect_kernel(const long long* __restrict__ ei) {
    int e = blockIdx.x * blockDim.x + threadIdx.x;
    if (e < NE) {
        long long v = ei[e];
        if (v < 0 || v >= NN) atomicAnd(&g_is64, 0);
    }
}

__device__ __forceinline__ int edge_row(const void* ei, int e) {
    return g_is64 ? (int)((const long long*)ei)[e] : ((const int*)ei)[e];
}
__device__ __forceinline__ int edge_col(const void* ei, int e) {
    return g_is64 ? (int)((const long long*)ei)[NE + e] : ((const int*)ei)[NE + e];
}

__global__ void count_kernel(const void* __restrict__ ei) {
    int e = blockIdx.x * blockDim.x + threadIdx.x;
    if (e < NE) atomicAdd(&g_cnt[edge_row(ei, e)], 1);
}

// 3-phase parallel scan
#define SCAN_NB ((NN + 255) / 256)   // 196
__global__ void scan1_kernel() {
    __shared__ int sh[256];
    int t = threadIdx.x, b = blockIdx.x;
    int i = b * 256 + t;
    int v = (i < NN) ? g_cnt[i] : 0;
    sh[t] = v; __syncthreads();
    for (int off = 1; off < 256; off <<= 1) {
        int u = (t >= off) ? sh[t - off] : 0;
        __syncthreads(); sh[t] += u; __syncthreads();
    }
    if (i < NN) g_rowptr[i] = sh[t] - v;
    if (t == 255) g_btot[b] = sh[255];
}
__global__ void scan2_kernel() {
    __shared__ int sh[256];
    int t = threadIdx.x;
    int v = (t < SCAN_NB) ? g_btot[t] : 0;
    sh[t] = v; __syncthreads();
    for (int off = 1; off < 256; off <<= 1) {
        int u = (t >= off) ? sh[t - off] : 0;
        __syncthreads(); sh[t] += u; __syncthreads();
    }
    if (t < SCAN_NB) g_btot[t] = sh[t] - v;
    if (t == SCAN_NB - 1) g_rowptr[NN] = sh[t];
}
__global__ void scan3_kernel() {
    int i = blockIdx.x * blockDim.x + threadIdx.x;
    if (i < NN) g_rowptr[i] += g_btot[i >> 8];
}

__global__ void scatter_kernel(const void* __restrict__ ei,
                               const float* __restrict__ ew) {
    int e = blockIdx.x * blockDim.x + threadIdx.x;
    if (e < NE) {
        int r = edge_row(ei, e);
        int c = edge_col(ei, e);
        int pos = g_rowptr[r] + atomicAdd(&g_fill[r], 1);
        g_cols[pos] = c;
        g_w[pos]    = ew[e];
    }
}

// ---------------- bf16x2 split conversions -----------------------------------
__device__ __forceinline__ uint32_t split_pack_hi(float a, float b,
                                                  float& ra, float& rb) {
    __nv_bfloat16 ha = __float2bfloat16_rn(a);
    __nv_bfloat16 hb = __float2bfloat16_rn(b);
    ra = a - __bfloat162float(ha);
    rb = b - __bfloat162float(hb);
    return (uint32_t)__bfloat16_as_ushort(ha) |
           ((uint32_t)__bfloat16_as_ushort(hb) << 16);
}
__device__ __forceinline__ uint32_t pack_bf16(float a, float b) {
    return (uint32_t)__bfloat16_as_ushort(__float2bfloat16_rn(a)) |
           ((uint32_t)__bfloat16_as_ushort(__float2bfloat16_rn(b)) << 16);
}

__global__ void convertA_kernel(const float* __restrict__ x) {
    int idx = blockIdx.x * blockDim.x + threadIdx.x;   // row*256 + k2
    if (idx >= NN * (KPAD / 2)) return;
    int row = idx >> 8;
    int k2  = idx & 255;
    float2 v = make_float2(0.f, 0.f);
    if (k2 < NF / 2)
        v = *(const float2*)(x + (size_t)row * NF + 2 * k2);
    float ra, rb;
    uint32_t hi = split_pack_hi(v.x, v.y, ra, rb);
    ((uint32_t*)g_A0)[idx] = hi;
    ((uint32_t*)g_A1)[idx] = pack_bf16(ra, rb);
}

__global__ void convertB_kernel(const float* __restrict__ Wa, const float* __restrict__ ba,
                                const float* __restrict__ Wb, const float* __restrict__ bb) {
    int idx = blockIdx.x * blockDim.x + threadIdx.x;   // n*256 + k2
    if (idx >= HID2 * (KPAD / 2)) return;
    int n  = idx >> 8;
    int k2 = idx & 255;
    int net = n >> 8;
    int col = n & (NH - 1);
    const float* W = net ? Wb : Wa;
    int k = 2 * k2;
    float a = (k     < NF) ? W[(size_t)k       * NH + col] : 0.f;
    float b = (k + 1 < NF) ? W[(size_t)(k + 1) * NH + col] : 0.f;
    float ra, rb;
    uint32_t hi = split_pack_hi(a, b, ra, rb);
    ((uint32_t*)g_B0)[idx] = hi;
    ((uint32_t*)g_B1)[idx] = pack_bf16(ra, rb);
    if (k2 == 0) g_bias[n] = net ? bb[col] : ba[col];
}

// ---------------- GEMM1 (mma.sync, cp.async 2-stage): H0 = A@B^T + bias ------
// CTA tile M=64, N=128, BK=64. 8 warps (2m x 4n), warp tile 32x32.
#define SM_BIAS   0
#define SM_STAGE0 1024
#define STG_A0    0
#define STG_A1    8192
#define STG_B0    16384
#define STG_B1    32768
#define STAGE_BYTES 49152
#define GEMM1_SMEM (SM_STAGE0 + 2 * STAGE_BYTES)   // 99328 bytes

__device__ __forceinline__ void load_stage(uint32_t stage_base, int mbase, int nbase,
                                           int k0, int tid) {
#pragma unroll
    for (int p = 0; p < 2; p++) {
        uint32_t off = (uint32_t)(tid + p * 256) * 16;   // 0..8176
        int row = off >> 7, inner = off & 127;
        int grow = mbase + row;
        int ok = (grow < NN) ? 16 : 0;
        int gr = (grow < NN) ? grow : (NN - 1);
        uint32_t sw = SMEM_SWIZZLE_128B(off);
        cp_async16(stage_base + STG_A0 + sw,
                   (const char*)g_A0 + ((size_t)gr * KPAD + k0) * 2 + inner, ok);
        cp_async16(stage_base + STG_A1 + sw,
                   (const char*)g_A1 + ((size_t)gr * KPAD + k0) * 2 + inner, ok);
    }
#pragma unroll
    for (int p = 0; p < 4; p++) {
        uint32_t off = (uint32_t)(tid + p * 256) * 16;   // 0..16368
        int row = off >> 7, inner = off & 127;
        int nrow = nbase + row;
        uint32_t sw = SMEM_SWIZZLE_128B(off);
        cp_async16(stage_base + STG_B0 + sw,
                   (const char*)g_B0 + ((size_t)nrow * KPAD + k0) * 2 + inner, 16);
        cp_async16(stage_base + STG_B1 + sw,
                   (const char*)g_B1 + ((size_t)nrow * KPAD + k0) * 2 + inner, 16);
    }
}

__device__ __forceinline__ uint32_t addrA(uint32_t base, int m_local, int k0, int lane) {
    int mat = lane >> 3, r = lane & 7;
    int m = m_local + r + (mat & 1) * 8;
    int k = k0 + (mat >> 1) * 8;
    return base + (uint32_t)(m * 128 + (((k >> 3) ^ (m & 7)) << 4));
}
__device__ __forceinline__ uint32_t addrB(uint32_t base, int n_local, int k0, int lane) {
    int mat = lane >> 3, r = lane & 7;
    int n = n_local + r + ((mat >> 1) & 1) * 8;
    int k = k0 + (mat & 1) * 8;
    return base + (uint32_t)(n * 128 + (((k >> 3) ^ (n & 7)) << 4));
}

__global__ __launch_bounds__(256, 2)
void gemm1_mma_kernel() {
    extern __shared__ char smem[];
    uint32_t sb = smem_u32(smem);
    int tid  = threadIdx.x;
    int lane = tid & 31, wid = tid >> 5;
    int warp_m = wid & 1;
    int warp_n = wid >> 1;
    int nbase = blockIdx.x * 128;
    int mbase = blockIdx.y * 64;

    if (tid < 32)
        ((float4*)(smem + SM_BIAS))[tid] = ((const float4*)(g_bias + nbase))[tid];

    float acc[2][4][4];
#pragma unroll
    for (int i = 0; i < 2; i++)
#pragma unroll
        for (int j = 0; j < 4; j++)
#pragma unroll
            for (int q = 0; q < 4; q++) acc[i][j][q] = 0.f;

    uint32_t stg[2] = { sb + SM_STAGE0, sb + SM_STAGE0 + STAGE_BYTES };

    load_stage(stg[0], mbase, nbase, 0, tid);
    CP_COMMIT();
    load_stage(stg[1], mbase, nbase, 64, tid);
    CP_COMMIT();

    for (int kt = 0; kt < 8; kt++) {
        int cur = kt & 1;
        if (kt < 7) CP_WAIT1(); else CP_WAIT0();
        __syncthreads();

        uint32_t sa0 = stg[cur] + STG_A0, sa1 = stg[cur] + STG_A1;
        uint32_t sb0 = stg[cur] + STG_B0, sb1 = stg[cur] + STG_B1;
#pragma unroll
        for (int ks = 0; ks < 4; ks++) {
            int k0 = ks * 16;
            uint32_t a[2][4], b[2][4];
#pragma unroll
            for (int mf = 0; mf < 2; mf++)
                ldsm_x4(a[mf], addrA(sa0, warp_m * 32 + mf * 16, k0, lane));
#pragma unroll
            for (int g = 0; g < 2; g++)
                ldsm_x4(b[g], addrB(sb0, warp_n * 32 + g * 16, k0, lane));
#pragma unroll
            for (int mf = 0; mf < 2; mf++)
#pragma unroll
                for (int nf = 0; nf < 4; nf++)
                    mma16816(acc[mf][nf], a[mf],
                             b[nf >> 1][(nf & 1) * 2], b[nf >> 1][(nf & 1) * 2 + 1]);
#pragma unroll
            for (int mf = 0; mf < 2; mf++)
                ldsm_x4(a[mf], addrA(sa1, warp_m * 32 + mf * 16, k0, lane));
#pragma unroll
            for (int mf = 0; mf < 2; mf++)
#pragma unroll
                for (int nf = 0; nf < 4; nf++)
                    mma16816(acc[mf][nf], a[mf],
                             b[nf >> 1][(nf & 1) * 2], b[nf >> 1][(nf & 1) * 2 + 1]);
#pragma unroll
            for (int mf = 0; mf < 2; mf++)
                ldsm_x4(a[mf], addrA(sa0, warp_m * 32 + mf * 16, k0, lane));
#pragma unroll
            for (int g = 0; g < 2; g++)
                ldsm_x4(b[g], addrB(sb1, warp_n * 32 + g * 16, k0, lane));
#pragma unroll
            for (int mf = 0; mf < 2; mf++)
#pragma unroll
                for (int nf = 0; nf < 4; nf++)
                    mma16816(acc[mf][nf], a[mf],
                             b[nf >> 1][(nf & 1) * 2], b[nf >> 1][(nf & 1) * 2 + 1]);
        }
        __syncthreads();
        if (kt + 2 < 8) {
            load_stage(stg[cur], mbase, nbase, (kt + 2) * 64, tid);
            CP_COMMIT();
        }
    }

    const float* bs = (const float*)(smem + SM_BIAS);
#pragma unroll
    for (int mf = 0; mf < 2; mf++) {
#pragma unroll
        for (int nf = 0; nf < 4; nf++) {
            int ncol = warp_n * 32 + nf * 8 + (lane & 3) * 2;
            float bx = bs[ncol], by = bs[ncol + 1];
            int r0 = mbase + warp_m * 32 + mf * 16 + (lane >> 2);
            if (r0 < NN) {
                float2 v = make_float2(acc[mf][nf][0] + bx, acc[mf][nf][1] + by);
                *(float2*)(g_H0 + (size_t)r0 * HID2 + nbase + ncol) = v;
            }
            int r1 = r0 + 8;
            if (r1 < NN) {
                float2 v = make_float2(acc[mf][nf][2] + bx, acc[mf][nf][3] + by);
                *(float2*)(g_H0 + (size_t)r1 * HID2 + nbase + ncol) = v;
            }
        }
    }
}

// ---------------- SPMM1 + ReLU + GEMM2, column-chunked -----------------------
// grid (NN/4, 4): chunk on y (slowest) -> phase-wise 25.6MB L2-resident set.
// warp w handles row bx*4+w, columns [chunk*128, chunk*128+128).
__global__ __launch_bounds__(128)
void spmm1_chunked_kernel(const float* __restrict__ W2a,
                          const float* __restrict__ W2b) {
    int warp = threadIdx.x >> 5, lane = threadIdx.x & 31;
    int r = blockIdx.x * 4 + warp;
    int chunk = blockIdx.y;              // 0..3
    if (r >= NN) return;

    const float4* H0c = (const float4*)(g_H0 + chunk * 128) + lane;
    float4 acc = make_float4(0.f, 0.f, 0.f, 0.f);
    int beg = g_rowptr[r], end = g_rowptr[r + 1];
    int e = beg;
    for (; e + 3 < end; e += 4) {
        int c0 = __ldg(&g_cols[e]),     c1 = __ldg(&g_cols[e + 1]);
        int c2 = __ldg(&g_cols[e + 2]), c3 = __ldg(&g_cols[e + 3]);
        float w0 = __ldg(&g_w[e]),     w1 = __ldg(&g_w[e + 1]);
        float w2 = __ldg(&g_w[e + 2]), w3 = __ldg(&g_w[e + 3]);
        float4 v0 = H0c[(size_t)c0 * 128];
        float4 v1 = H0c[(size_t)c1 * 128];
        float4 v2 = H0c[(size_t)c2 * 128];
        float4 v3 = H0c[(size_t)c3 * 128];
        acc.x += w0 * v0.x + w1 * v1.x + w2 * v2.x + w3 * v3.x;
        acc.y += w0 * v0.y + w1 * v1.y + w2 * v2.y + w3 * v3.y;
        acc.z += w0 * v0.z + w1 * v1.z + w2 * v2.z + w3 * v3.z;
        acc.w += w0 * v0.w + w1 * v1.w + w2 * v2.w + w3 * v3.w;
    }
    for (; e < end; e++) {
        int c0 = __ldg(&g_cols[e]);
        float w0 = __ldg(&g_w[e]);
        float4 v0 = H0c[(size_t)c0 * 128];
        acc.x += w0 * v0.x; acc.y += w0 * v0.y;
        acc.z += w0 * v0.z; acc.w += w0 * v0.w;
    }
    float h[4];
    h[0] = fmaxf(acc.x, 0.f); h[1] = fmaxf(acc.y, 0.f);
    h[2] = fmaxf(acc.z, 0.f); h[3] = fmaxf(acc.w, 0.f);

    // partial dense layer for this chunk's 128 columns
    int net   = chunk >> 1;              // chunks 0,1 -> net0; 2,3 -> net1
    int kbase = (chunk & 1) * 128;       // offset within the net's 256 cols
    const float* W = net ? W2b : W2a;
    int krow = kbase + lane * 4;
#pragma unroll
    for (int cc = 0; cc < NC; cc++) {
        float s = h[0] * __ldg(&W[(krow + 0) * NC + cc])
                + h[1] * __ldg(&W[(krow + 1) * NC + cc])
                + h[2] * __ldg(&W[(krow + 2) * NC + cc])
                + h[3] * __ldg(&W[(krow + 3) * NC + cc]);
#pragma unroll
        for (int o = 16; o; o >>= 1) s += __shfl_xor_sync(0xFFFFFFFFu, s, o);
        if (lane == 0)
            atomicAdd(&g_H2[(size_t)r * 2 * NC + net * NC + cc], s);
    }
}

// ---------------- SPMM2 -> output: warp per row, 20 active lanes -------------
__global__ __launch_bounds__(256)
void spmm2_kernel(float* __restrict__ out) {
    int gid  = blockIdx.x * blockDim.x + threadIdx.x;
    int warp = gid >> 5;
    int lane = threadIdx.x & 31;
    if (warp >= NN) return;
    int beg = g_rowptr[warp], end = g_rowptr[warp + 1];
    float acc = 0.f;
    for (int e = beg; e < end; e++) {
        int c = __ldg(&g_cols[e]);
        float w = __ldg(&g_w[e]);
        if (lane < 2 * NC) acc += w * g_H2[(size_t)c * 2 * NC + lane];
    }
    if (lane < NC)
        out[(size_t)warp * NC + lane] = acc;
    else if (lane < 2 * NC)
        out[(size_t)NN * NC + (size_t)warp * NC + (lane - NC)] = acc;
}

// ---------------- launch -----------------------------------------------------
extern "C" void kernel_launch(void* const* d_in, const int* in_sizes, int n_in,
                              void* d_out, int out_size) {
    const float* x    = (const float*)d_in[0];
    const void*  ei   = d_in[1];
    const float* ew   = (const float*)d_in[2];
    const float* W1a  = (const float*)d_in[3];
    const float* b1a  = (const float*)d_in[4];
    const float* W2a  = (const float*)d_in[5];
    const float* b2a  = (const float*)d_in[6];
    const float* W1b  = (const float*)d_in[7];
    const float* b1b  = (const float*)d_in[8];
    const float* W2b  = (const float*)d_in[9];
    const float* b2b  = (const float*)d_in[10];
    float* out = (float*)d_out;

    cudaFuncSetAttribute(gemm1_mma_kernel,
                         cudaFuncAttributeMaxDynamicSharedMemorySize, GEMM1_SMEM);

    // converts first so gemm1 is launch #3 (ncu sampling window)
    convertA_kernel<<<(NN * (KPAD / 2) + 255) / 256, 256>>>(x);
    convertB_kernel<<<(HID2 * (KPAD / 2) + 255) / 256, 256>>>(W1a, b1a, W1b, b1b);
    initH2_kernel<<<(NN * 2 * NC + 255) / 256, 256>>>(b2a, b2b);

    dim3 g1(HID2 / 128, (NN + 63) / 64);
    gemm1_mma_kernel<<<g1, 256, GEMM1_SMEM>>>();

    // CSR build (dtype-safe, graph-capturable)
    zero_kernel<<<(NN + 255) / 256, 256>>>();
    detect_kernel<<<(NE + 255) / 256, 256>>>((const long long*)ei);
    count_kernel<<<(NE + 255) / 256, 256>>>(ei);
    scan1_kernel<<<SCAN_NB, 256>>>();
    scan2_kernel<<<1, 256>>>();
    scan3_kernel<<<(NN + 255) / 256, 256>>>();
    scatter_kernel<<<(NE + 255) / 256, 256>>>(ei, ew);

    // propagate + relu + layer-2 linear, column-chunked for L2 residency
    dim3 gs((NN + 3) / 4, 4);
    spmm1_chunked_kernel<<<gs, 128>>>(W2a, W2b);

    // propagate -> outputs
    spmm2_kernel<<<(NN * 32 + 255) / 256, 256>>>(out);
}

// round 10
// speedup vs baseline: 1.0756x; 1.0756x over previous
#include <cuda_runtime.h>
#include <cuda_bf16.h>
#include <cstdint>

#define NN 50000
#define NE 800000
#define NF 500
#define NH 256
#define NC 10
#define HID2 512   // both networks' hidden concatenated
#define KPAD 512   // padded K for tensor-core GEMM

// ---------------- scratch (device globals; no runtime allocation) -----------
__device__ __align__(256) float g_H0[NN * HID2];   // x@W1 + b1 (both nets)
__device__ __align__(256) float g_H2[NN * 2 * NC]; // relu(spmm(H0)) @ W2 + b2
__device__ __align__(256) __nv_bfloat16 g_A0[NN * KPAD];   // hi(x), K-padded
__device__ __align__(256) __nv_bfloat16 g_A1[NN * KPAD];   // lo(x)
__device__ __align__(256) __nv_bfloat16 g_B0[HID2 * KPAD]; // hi(W^T) [n][k]
__device__ __align__(256) __nv_bfloat16 g_B1[HID2 * KPAD]; // lo(W^T)
__device__ __align__(256) float g_bias[HID2];
__device__ int   g_rowptr[NN + 1];
__device__ int   g_cnt[NN];
__device__ int   g_fill[NN];
__device__ int   g_btot[256];
__device__ int   g_cols[NE];
__device__ float g_w[NE];
__device__ int   g_is64;

// ================= helpers ===================================================
__device__ __forceinline__ uint32_t smem_u32(const void* p) {
    uint32_t a;
    asm("{ .reg .u64 t; cvta.to.shared.u64 t, %1; cvt.u32.u64 %0, t; }"
        : "=r"(a) : "l"(p));
    return a;
}
#define SMEM_SWIZZLE_128B(off) ((off) ^ (((off) >> 3) & 0x70))

__device__ __forceinline__ void ldsm_x4(uint32_t* d, uint32_t addr) {
    asm volatile("ldmatrix.sync.aligned.m8n8.x4.shared.b16 {%0,%1,%2,%3}, [%4];"
                 : "=r"(d[0]), "=r"(d[1]), "=r"(d[2]), "=r"(d[3]) : "r"(addr));
}
__device__ __forceinline__ void mma16816(float* c, const uint32_t* a,
                                         uint32_t b0, uint32_t b1) {
    asm volatile("mma.sync.aligned.m16n8k16.row.col.f32.bf16.bf16.f32 "
                 "{%0,%1,%2,%3}, {%4,%5,%6,%7}, {%8,%9}, {%0,%1,%2,%3};"
                 : "+f"(c[0]), "+f"(c[1]), "+f"(c[2]), "+f"(c[3])
                 : "r"(a[0]), "r"(a[1]), "r"(a[2]), "r"(a[3]), "r"(b0), "r"(b1));
}
__device__ __forceinline__ void cp_async16(uint32_t dst, const void* src, int src_sz) {
    asm volatile("cp.async.cg.shared.global [%0], [%1], 16, %2;"
                 :: "r"(dst), "l"(src), "r"(src_sz) : "memory");
}
#define CP_COMMIT() asm volatile("cp.async.commit_group;" ::: "memory")
#define CP_WAIT1()  asm volatile("cp.async.wait_group 1;" ::: "memory")
#define CP_WAIT0()  asm volatile("cp.async.wait_group 0;" ::: "memory")
#define CP_WAIT5()  asm volatile("cp.async.wait_group 5;" ::: "memory")

// ---------------- dtype detect + CSR build ----------------------------------
__global__ void zero_kernel() {
    int i = blockIdx.x * blockDim.x + threadIdx.x;
    if (i < NN) { g_cnt[i] = 0; g_fill[i] = 0; }
    if (i == 0) g_is64 = 1;
}

__global__ void detect_kernel(const long long* __restrict__ ei) {
    int e = blockIdx.x * blockDim.x + threadIdx.x;
    if (e < NE) {
        long long v = ei[e];
        if (v < 0 || v >= NN) atomicAnd(&g_is64, 0);
    }
}

__device__ __forceinline__ int edge_row(const void* ei, int e) {
    return g_is64 ? (int)((const long long*)ei)[e] : ((const int*)ei)[e];
}
__device__ __forceinline__ int edge_col(const void* ei, int e) {
    return g_is64 ? (int)((const long long*)ei)[NE + e] : ((const int*)ei)[NE + e];
}

__global__ void count_kernel(const void* __restrict__ ei) {
    int e = blockIdx.x * blockDim.x + threadIdx.x;
    if (e < NE) atomicAdd(&g_cnt[edge_row(ei, e)], 1);
}

// 3-phase parallel scan
#define SCAN_NB ((NN + 255) / 256)   // 196
__global__ void scan1_kernel() {
    __shared__ int sh[256];
    int t = threadIdx.x, b = blockIdx.x;
    int i = b * 256 + t;
    int v = (i < NN) ? g_cnt[i] : 0;
    sh[t] = v; __syncthreads();
    for (int off = 1; off < 256; off <<= 1) {
        int u = (t >= off) ? sh[t - off] : 0;
        __syncthreads(); sh[t] += u; __syncthreads();
    }
    if (i < NN) g_rowptr[i] = sh[t] - v;
    if (t == 255) g_btot[b] = sh[255];
}
__global__ void scan2_kernel() {
    __shared__ int sh[256];
    int t = threadIdx.x;
    int v = (t < SCAN_NB) ? g_btot[t] : 0;
    sh[t] = v; __syncthreads();
    for (int off = 1; off < 256; off <<= 1) {
        int u = (t >= off) ? sh[t - off] : 0;
        __syncthreads(); sh[t] += u; __syncthreads();
    }
    if (t < SCAN_NB) g_btot[t] = sh[t] - v;
    if (t == SCAN_NB - 1) g_rowptr[NN] = sh[t];
}
__global__ void scan3_kernel() {
    int i = blockIdx.x * blockDim.x + threadIdx.x;
    if (i < NN) g_rowptr[i] += g_btot[i >> 8];
}

__global__ void scatter_kernel(const void* __restrict__ ei,
                               const float* __restrict__ ew) {
    int e = blockIdx.x * blockDim.x + threadIdx.x;
    if (e < NE) {
        int r = edge_row(ei, e);
        int c = edge_col(ei, e);
        int pos = g_rowptr[r] + atomicAdd(&g_fill[r], 1);
        g_cols[pos] = c;
        g_w[pos]    = ew[e];
    }
}

// ---------------- bf16x2 split conversions -----------------------------------
__device__ __forceinline__ uint32_t split_pack_hi(float a, float b,
                                                  float& ra, float& rb) {
    __nv_bfloat16 ha = __float2bfloat16_rn(a);
    __nv_bfloat16 hb = __float2bfloat16_rn(b);
    ra = a - __bfloat162float(ha);
    rb = b - __bfloat162float(hb);
    return (uint32_t)__bfloat16_as_ushort(ha) |
           ((uint32_t)__bfloat16_as_ushort(hb) << 16);
}
__device__ __forceinline__ uint32_t pack_bf16(float a, float b) {
    return (uint32_t)__bfloat16_as_ushort(__float2bfloat16_rn(a)) |
           ((uint32_t)__bfloat16_as_ushort(__float2bfloat16_rn(b)) << 16);
}

__global__ void convertA_kernel(const float* __restrict__ x) {
    int idx = blockIdx.x * blockDim.x + threadIdx.x;   // row*256 + k2
    if (idx >= NN * (KPAD / 2)) return;
    int row = idx >> 8;
    int k2  = idx & 255;
    float2 v = make_float2(0.f, 0.f);
    if (k2 < NF / 2)
        v = *(const float2*)(x + (size_t)row * NF + 2 * k2);
    float ra, rb;
    uint32_t hi = split_pack_hi(v.x, v.y, ra, rb);
    ((uint32_t*)g_A0)[idx] = hi;
    ((uint32_t*)g_A1)[idx] = pack_bf16(ra, rb);
}

__global__ void convertB_kernel(const float* __restrict__ Wa, const float* __restrict__ ba,
                                const float* __restrict__ Wb, const float* __restrict__ bb) {
    int idx = blockIdx.x * blockDim.x + threadIdx.x;   // n*256 + k2
    if (idx >= HID2 * (KPAD / 2)) return;
    int n  = idx >> 8;
    int k2 = idx & 255;
    int net = n >> 8;
    int col = n & (NH - 1);
    const float* W = net ? Wb : Wa;
    int k = 2 * k2;
    float a = (k     < NF) ? W[(size_t)k       * NH + col] : 0.f;
    float b = (k + 1 < NF) ? W[(size_t)(k + 1) * NH + col] : 0.f;
    float ra, rb;
    uint32_t hi = split_pack_hi(a, b, ra, rb);
    ((uint32_t*)g_B0)[idx] = hi;
    ((uint32_t*)g_B1)[idx] = pack_bf16(ra, rb);
    if (k2 == 0) g_bias[n] = net ? bb[col] : ba[col];
}

// ---------------- GEMM1 (mma.sync, cp.async 2-stage): H0 = A@B^T + bias ------
#define SM_BIAS   0
#define SM_STAGE0 1024
#define STG_A0    0
#define STG_A1    8192
#define STG_B0    16384
#define STG_B1    32768
#define STAGE_BYTES 49152
#define GEMM1_SMEM (SM_STAGE0 + 2 * STAGE_BYTES)   // 99328 bytes

__device__ __forceinline__ void load_stage(uint32_t stage_base, int mbase, int nbase,
                                           int k0, int tid) {
#pragma unroll
    for (int p = 0; p < 2; p++) {
        uint32_t off = (uint32_t)(tid + p * 256) * 16;
        int row = off >> 7, inner = off & 127;
        int grow = mbase + row;
        int ok = (grow < NN) ? 16 : 0;
        int gr = (grow < NN) ? grow : (NN - 1);
        uint32_t sw = SMEM_SWIZZLE_128B(off);
        cp_async16(stage_base + STG_A0 + sw,
                   (const char*)g_A0 + ((size_t)gr * KPAD + k0) * 2 + inner, ok);
        cp_async16(stage_base + STG_A1 + sw,
                   (const char*)g_A1 + ((size_t)gr * KPAD + k0) * 2 + inner, ok);
    }
#pragma unroll
    for (int p = 0; p < 4; p++) {
        uint32_t off = (uint32_t)(tid + p * 256) * 16;
        int row = off >> 7, inner = off & 127;
        int nrow = nbase + row;
        uint32_t sw = SMEM_SWIZZLE_128B(off);
        cp_async16(stage_base + STG_B0 + sw,
                   (const char*)g_B0 + ((size_t)nrow * KPAD + k0) * 2 + inner, 16);
        cp_async16(stage_base + STG_B1 + sw,
                   (const char*)g_B1 + ((size_t)nrow * KPAD + k0) * 2 + inner, 16);
    }
}

__device__ __forceinline__ uint32_t addrA(uint32_t base, int m_local, int k0, int lane) {
    int mat = lane >> 3, r = lane & 7;
    int m = m_local + r + (mat & 1) * 8;
    int k = k0 + (mat >> 1) * 8;
    return base + (uint32_t)(m * 128 + (((k >> 3) ^ (m & 7)) << 4));
}
__device__ __forceinline__ uint32_t addrB(uint32_t base, int n_local, int k0, int lane) {
    int mat = lane >> 3, r = lane & 7;
    int n = n_local + r + ((mat >> 1) & 1) * 8;
    int k = k0 + (mat & 1) * 8;
    return base + (uint32_t)(n * 128 + (((k >> 3) ^ (n & 7)) << 4));
}

__global__ __launch_bounds__(256, 2)
void gemm1_mma_kernel() {
    extern __shared__ char smem[];
    uint32_t sb = smem_u32(smem);
    int tid  = threadIdx.x;
    int lane = tid & 31, wid = tid >> 5;
    int warp_m = wid & 1;
    int warp_n = wid >> 1;
    int nbase = blockIdx.x * 128;
    int mbase = blockIdx.y * 64;

    if (tid < 32)
        ((float4*)(smem + SM_BIAS))[tid] = ((const float4*)(g_bias + nbase))[tid];

    float acc[2][4][4];
#pragma unroll
    for (int i = 0; i < 2; i++)
#pragma unroll
        for (int j = 0; j < 4; j++)
#pragma unroll
            for (int q = 0; q < 4; q++) acc[i][j][q] = 0.f;

    uint32_t stg[2] = { sb + SM_STAGE0, sb + SM_STAGE0 + STAGE_BYTES };

    load_stage(stg[0], mbase, nbase, 0, tid);
    CP_COMMIT();
    load_stage(stg[1], mbase, nbase, 64, tid);
    CP_COMMIT();

    for (int kt = 0; kt < 8; kt++) {
        int cur = kt & 1;
        if (kt < 7) CP_WAIT1(); else CP_WAIT0();
        __syncthreads();

        uint32_t sa0 = stg[cur] + STG_A0, sa1 = stg[cur] + STG_A1;
        uint32_t sb0 = stg[cur] + STG_B0, sb1 = stg[cur] + STG_B1;
#pragma unroll
        for (int ks = 0; ks < 4; ks++) {
            int k0 = ks * 16;
            uint32_t a[2][4], b[2][4];
#pragma unroll
            for (int mf = 0; mf < 2; mf++)
                ldsm_x4(a[mf], addrA(sa0, warp_m * 32 + mf * 16, k0, lane));
#pragma unroll
            for (int g = 0; g < 2; g++)
                ldsm_x4(b[g], addrB(sb0, warp_n * 32 + g * 16, k0, lane));
#pragma unroll
            for (int mf = 0; mf < 2; mf++)
#pragma unroll
                for (int nf = 0; nf < 4; nf++)
                    mma16816(acc[mf][nf], a[mf],
                             b[nf >> 1][(nf & 1) * 2], b[nf >> 1][(nf & 1) * 2 + 1]);
#pragma unroll
            for (int mf = 0; mf < 2; mf++)
                ldsm_x4(a[mf], addrA(sa1, warp_m * 32 + mf * 16, k0, lane));
#pragma unroll
            for (int mf = 0; mf < 2; mf++)
#pragma unroll
                for (int nf = 0; nf < 4; nf++)
                    mma16816(acc[mf][nf], a[mf],
                             b[nf >> 1][(nf & 1) * 2], b[nf >> 1][(nf & 1) * 2 + 1]);
#pragma unroll
            for (int mf = 0; mf < 2; mf++)
                ldsm_x4(a[mf], addrA(sa0, warp_m * 32 + mf * 16, k0, lane));
#pragma unroll
            for (int g = 0; g < 2; g++)
                ldsm_x4(b[g], addrB(sb1, warp_n * 32 + g * 16, k0, lane));
#pragma unroll
            for (int mf = 0; mf < 2; mf++)
#pragma unroll
                for (int nf = 0; nf < 4; nf++)
                    mma16816(acc[mf][nf], a[mf],
                             b[nf >> 1][(nf & 1) * 2], b[nf >> 1][(nf & 1) * 2 + 1]);
        }
        __syncthreads();
        if (kt + 2 < 8) {
            load_stage(stg[cur], mbase, nbase, (kt + 2) * 64, tid);
            CP_COMMIT();
        }
    }

    const float* bs = (const float*)(smem + SM_BIAS);
#pragma unroll
    for (int mf = 0; mf < 2; mf++) {
#pragma unroll
        for (int nf = 0; nf < 4; nf++) {
            int ncol = warp_n * 32 + nf * 8 + (lane & 3) * 2;
            float bx = bs[ncol], by = bs[ncol + 1];
            int r0 = mbase + warp_m * 32 + mf * 16 + (lane >> 2);
            if (r0 < NN) {
                float2 v = make_float2(acc[mf][nf][0] + bx, acc[mf][nf][1] + by);
                *(float2*)(g_H0 + (size_t)r0 * HID2 + nbase + ncol) = v;
            }
            int r1 = r0 + 8;
            if (r1 < NN) {
                float2 v = make_float2(acc[mf][nf][2] + bx, acc[mf][nf][3] + by);
                *(float2*)(g_H0 + (size_t)r1 * HID2 + nbase + ncol) = v;
            }
        }
    }
}

// ---------------- SPMM1 + ReLU + GEMM2, cp.async pipelined -------------------
// block per row; each thread streams its own 16B slice of each edge's H0 row
// through a 6-deep smem ring (per-thread cp.async groups -> MLP=6, no syncs).
#define PDEPTH 6
__global__ __launch_bounds__(128)
void spmm1_fused_kernel(const float* __restrict__ W2a, const float* __restrict__ b2a,
                        const float* __restrict__ W2b, const float* __restrict__ b2b) {
    __shared__ __align__(16) float buf[PDEPTH * HID2];  // 12 KB ring
    __shared__ __align__(16) float sh[HID2];            // 2 KB h1 row
    int r = blockIdx.x;
    int t = threadIdx.x;
    int beg = g_rowptr[r], end = g_rowptr[r + 1];
    int deg = end - beg;

    uint32_t my_slot = smem_u32(buf) + (uint32_t)t * 16;
    const char* H0b = (const char*)g_H0 + (size_t)t * 16;

    // prologue: fill the ring
#pragma unroll
    for (int d = 0; d < PDEPTH; d++) {
        if (d < deg) {
            int c = __ldg(&g_cols[beg + d]);
            cp_async16(my_slot + (uint32_t)d * 2048, H0b + (size_t)c * 2048, 16);
        }
        CP_COMMIT();
    }

    float4 acc = make_float4(0.f, 0.f, 0.f, 0.f);
    int stage = 0;
    for (int e = beg; e < end; e++) {
        CP_WAIT5();                       // oldest group done
        float w = __ldg(&g_w[e]);
        float4 v = *(const float4*)((const char*)buf + (size_t)stage * 2048 +
                                    (size_t)t * 16);
        acc.x += w * v.x; acc.y += w * v.y;
        acc.z += w * v.z; acc.w += w * v.w;
        int en = e + PDEPTH;
        if (en < end) {
            int c = __ldg(&g_cols[en]);
            cp_async16(my_slot + (uint32_t)stage * 2048, H0b + (size_t)c * 2048, 16);
        }
        CP_COMMIT();
        if (++stage == PDEPTH) stage = 0;
    }

    float4 h;
    h.x = fmaxf(acc.x, 0.f); h.y = fmaxf(acc.y, 0.f);
    h.z = fmaxf(acc.z, 0.f); h.w = fmaxf(acc.w, 0.f);
    ((float4*)sh)[t] = h;
    __syncthreads();

    // dense layer: 20 outputs over 4 warps (5 each)
    int warp = t >> 5, lane = t & 31;
#pragma unroll
    for (int j = 0; j < 5; j++) {
        int c   = warp * 5 + j;          // 0..19
        int net = (c >= NC) ? 1 : 0;
        int cc  = c - net * NC;
        const float* W = net ? W2b : W2a;
        const float* hh = sh + net * NH;
        float s = 0.f;
#pragma unroll
        for (int i = 0; i < NH / 32; i++) {
            int k = lane + i * 32;
            s += hh[k] * __ldg(&W[(size_t)k * NC + cc]);
        }
#pragma unroll
        for (int o = 16; o; o >>= 1) s += __shfl_xor_sync(0xFFFFFFFFu, s, o);
        if (lane == 0)
            g_H2[(size_t)r * 2 * NC + c] =
                s + (net ? __ldg(&b2b[cc]) : __ldg(&b2a[cc]));
    }
}

// ---------------- SPMM2 -> output: warp per row, 20 active lanes -------------
__global__ __launch_bounds__(256)
void spmm2_kernel(float* __restrict__ out) {
    int gid  = blockIdx.x * blockDim.x + threadIdx.x;
    int warp = gid >> 5;
    int lane = threadIdx.x & 31;
    if (warp >= NN) return;
    int beg = g_rowptr[warp], end = g_rowptr[warp + 1];
    float acc = 0.f;
    for (int e = beg; e < end; e++) {
        int c = __ldg(&g_cols[e]);
        float w = __ldg(&g_w[e]);
        if (lane < 2 * NC) acc += w * g_H2[(size_t)c * 2 * NC + lane];
    }
    if (lane < NC)
        out[(size_t)warp * NC + lane] = acc;
    else if (lane < 2 * NC)
        out[(size_t)NN * NC + (size_t)warp * NC + (lane - NC)] = acc;
}

// ---------------- launch -----------------------------------------------------
extern "C" void kernel_launch(void* const* d_in, const int* in_sizes, int n_in,
                              void* d_out, int out_size) {
    const float* x    = (const float*)d_in[0];
    const void*  ei   = d_in[1];
    const float* ew   = (const float*)d_in[2];
    const float* W1a  = (const float*)d_in[3];
    const float* b1a  = (const float*)d_in[4];
    const float* W2a  = (const float*)d_in[5];
    const float* b2a  = (const float*)d_in[6];
    const float* W1b  = (const float*)d_in[7];
    const float* b1b  = (const float*)d_in[8];
    const float* W2b  = (const float*)d_in[9];
    const float* b2b  = (const float*)d_in[10];
    float* out = (float*)d_out;

    cudaFuncSetAttribute(gemm1_mma_kernel,
                         cudaFuncAttributeMaxDynamicSharedMemorySize, GEMM1_SMEM);

    // order chosen so gemm1 sits in the profiled 4th launch slot
    convertA_kernel<<<(NN * (KPAD / 2) + 255) / 256, 256>>>(x);
    convertB_kernel<<<(HID2 * (KPAD / 2) + 255) / 256, 256>>>(W1a, b1a, W1b, b1b);
    zero_kernel<<<(NN + 255) / 256, 256>>>();

    dim3 g1(HID2 / 128, (NN + 63) / 64);
    gemm1_mma_kernel<<<g1, 256, GEMM1_SMEM>>>();

    // CSR build (dtype-safe, graph-capturable)
    detect_kernel<<<(NE + 255) / 256, 256>>>((const long long*)ei);
    count_kernel<<<(NE + 255) / 256, 256>>>(ei);
    scan1_kernel<<<SCAN_NB, 256>>>();
    scan2_kernel<<<1, 256>>>();
    scan3_kernel<<<(NN + 255) / 256, 256>>>();
    scatter_kernel<<<(NE + 255) / 256, 256>>>(ei, ew);

    // propagate + relu + layer-2 linear (fused, cp.async pipelined)
    spmm1_fused_kernel<<<NN, 128>>>(W2a, b2a, W2b, b2b);

    // propagate -> outputs
    spmm2_kernel<<<(NN * 32 + 255) / 256, 256>>>(out);
}

// round 11
// speedup vs baseline: 1.2173x; 1.1318x over previous
#include <cuda_runtime.h>
#include <cuda_bf16.h>
#include <cuda_fp16.h>
#include <cstdint>

#define NN 50000
#define NE 800000
#define NF 500
#define NH 256
#define NC 10
#define HID2 512   // both networks' hidden concatenated
#define KPAD 512   // padded K for tensor-core GEMM

// ---------------- scratch (device globals; no runtime allocation) -----------
__device__ __align__(256) __half g_H0h[NN * HID2]; // x@W1 + b1 (fp16, 51MB)
__device__ __align__(256) float g_H2[NN * 2 * NC]; // relu(spmm(H0)) @ W2 + b2
__device__ __align__(256) __nv_bfloat16 g_A0[NN * KPAD];   // hi(x), K-padded
__device__ __align__(256) __nv_bfloat16 g_A1[NN * KPAD];   // lo(x)
__device__ __align__(256) __nv_bfloat16 g_B0[HID2 * KPAD]; // hi(W^T) [n][k]
__device__ __align__(256) __nv_bfloat16 g_B1[HID2 * KPAD]; // lo(W^T)
__device__ __align__(256) float g_bias[HID2];
__device__ int   g_rowptr[NN + 1];
__device__ int   g_cnt[NN];
__device__ int   g_fill[NN];
__device__ int   g_btot[256];
__device__ int   g_cols[NE];
__device__ float g_w[NE];
__device__ int   g_is64;

// ================= helpers ===================================================
__device__ __forceinline__ uint32_t smem_u32(const void* p) {
    uint32_t a;
    asm("{ .reg .u64 t; cvta.to.shared.u64 t, %1; cvt.u32.u64 %0, t; }"
        : "=r"(a) : "l"(p));
    return a;
}
#define SMEM_SWIZZLE_128B(off) ((off) ^ (((off) >> 3) & 0x70))

__device__ __forceinline__ void ldsm_x4(uint32_t* d, uint32_t addr) {
    asm volatile("ldmatrix.sync.aligned.m8n8.x4.shared.b16 {%0,%1,%2,%3}, [%4];"
                 : "=r"(d[0]), "=r"(d[1]), "=r"(d[2]), "=r"(d[3]) : "r"(addr));
}
__device__ __forceinline__ void mma16816(float* c, const uint32_t* a,
                                         uint32_t b0, uint32_t b1) {
    asm volatile("mma.sync.aligned.m16n8k16.row.col.f32.bf16.bf16.f32 "
                 "{%0,%1,%2,%3}, {%4,%5,%6,%7}, {%8,%9}, {%0,%1,%2,%3};"
                 : "+f"(c[0]), "+f"(c[1]), "+f"(c[2]), "+f"(c[3])
                 : "r"(a[0]), "r"(a[1]), "r"(a[2]), "r"(a[3]), "r"(b0), "r"(b1));
}
__device__ __forceinline__ void cp_async16(uint32_t dst, const void* src, int src_sz) {
    asm volatile("cp.async.cg.shared.global [%0], [%1], 16, %2;"
                 :: "r"(dst), "l"(src), "r"(src_sz) : "memory");
}
#define CP_COMMIT() asm volatile("cp.async.commit_group;" ::: "memory")
#define CP_WAIT1()  asm volatile("cp.async.wait_group 1;" ::: "memory")
#define CP_WAIT0()  asm volatile("cp.async.wait_group 0;" ::: "memory")

// ---------------- dtype detect + CSR build ----------------------------------
__global__ void zero_kernel() {
    int i = blockIdx.x * blockDim.x + threadIdx.x;
    if (i < NN) { g_cnt[i] = 0; g_fill[i] = 0; }
    if (i == 0) g_is64 = 1;
}

__global__ void detect_kernel(const long long* __restrict__ ei) {
    int e = blockIdx.x * blockDim.x + threadIdx.x;
    if (e < NE) {
        long long v = ei[e];
        if (v < 0 || v >= NN) atomicAnd(&g_is64, 0);
    }
}

__device__ __forceinline__ int edge_row(const void* ei, int e) {
    return g_is64 ? (int)((const long long*)ei)[e] : ((const int*)ei)[e];
}
__device__ __forceinline__ int edge_col(const void* ei, int e) {
    return g_is64 ? (int)((const long long*)ei)[NE + e] : ((const int*)ei)[NE + e];
}

__global__ void count_kernel(const void* __restrict__ ei) {
    int e = blockIdx.x * blockDim.x + threadIdx.x;
    if (e < NE) atomicAdd(&g_cnt[edge_row(ei, e)], 1);
}

// 3-phase parallel scan
#define SCAN_NB ((NN + 255) / 256)   // 196
__global__ void scan1_kernel() {
    __shared__ int sh[256];
    int t = threadIdx.x, b = blockIdx.x;
    int i = b * 256 + t;
    int v = (i < NN) ? g_cnt[i] : 0;
    sh[t] = v; __syncthreads();
    for (int off = 1; off < 256; off <<= 1) {
        int u = (t >= off) ? sh[t - off] : 0;
        __syncthreads(); sh[t] += u; __syncthreads();
    }
    if (i < NN) g_rowptr[i] = sh[t] - v;
    if (t == 255) g_btot[b] = sh[255];
}
__global__ void scan2_kernel() {
    __shared__ int sh[256];
    int t = threadIdx.x;
    int v = (t < SCAN_NB) ? g_btot[t] : 0;
    sh[t] = v; __syncthreads();
    for (int off = 1; off < 256; off <<= 1) {
        int u = (t >= off) ? sh[t - off] : 0;
        __syncthreads(); sh[t] += u; __syncthreads();
    }
    if (t < SCAN_NB) g_btot[t] = sh[t] - v;
    if (t == SCAN_NB - 1) g_rowptr[NN] = sh[t];
}
__global__ void scan3_kernel() {
    int i = blockIdx.x * blockDim.x + threadIdx.x;
    if (i < NN) g_rowptr[i] += g_btot[i >> 8];
}

__global__ void scatter_kernel(const void* __restrict__ ei,
                               const float* __restrict__ ew) {
    int e = blockIdx.x * blockDim.x + threadIdx.x;
    if (e < NE) {
        int r = edge_row(ei, e);
        int c = edge_col(ei, e);
        int pos = g_rowptr[r] + atomicAdd(&g_fill[r], 1);
        g_cols[pos] = c;
        g_w[pos]    = ew[e];
    }
}

// ---------------- bf16x2 split conversions -----------------------------------
__device__ __forceinline__ uint32_t split_pack_hi(float a, float b,
                                                  float& ra, float& rb) {
    __nv_bfloat16 ha = __float2bfloat16_rn(a);
    __nv_bfloat16 hb = __float2bfloat16_rn(b);
    ra = a - __bfloat162float(ha);
    rb = b - __bfloat162float(hb);
    return (uint32_t)__bfloat16_as_ushort(ha) |
           ((uint32_t)__bfloat16_as_ushort(hb) << 16);
}
__device__ __forceinline__ uint32_t pack_bf16(float a, float b) {
    return (uint32_t)__bfloat16_as_ushort(__float2bfloat16_rn(a)) |
           ((uint32_t)__bfloat16_as_ushort(__float2bfloat16_rn(b)) << 16);
}

__global__ void convertA_kernel(const float* __restrict__ x) {
    int idx = blockIdx.x * blockDim.x + threadIdx.x;   // row*256 + k2
    if (idx >= NN * (KPAD / 2)) return;
    int row = idx >> 8;
    int k2  = idx & 255;
    float2 v = make_float2(0.f, 0.f);
    if (k2 < NF / 2)
        v = *(const float2*)(x + (size_t)row * NF + 2 * k2);
    float ra, rb;
    uint32_t hi = split_pack_hi(v.x, v.y, ra, rb);
    ((uint32_t*)g_A0)[idx] = hi;
    ((uint32_t*)g_A1)[idx] = pack_bf16(ra, rb);
}

__global__ void convertB_kernel(const float* __restrict__ Wa, const float* __restrict__ ba,
                                const float* __restrict__ Wb, const float* __restrict__ bb) {
    int idx = blockIdx.x * blockDim.x + threadIdx.x;   // n*256 + k2
    if (idx >= HID2 * (KPAD / 2)) return;
    int n  = idx >> 8;
    int k2 = idx & 255;
    int net = n >> 8;
    int col = n & (NH - 1);
    const float* W = net ? Wb : Wa;
    int k = 2 * k2;
    float a = (k     < NF) ? W[(size_t)k       * NH + col] : 0.f;
    float b = (k + 1 < NF) ? W[(size_t)(k + 1) * NH + col] : 0.f;
    float ra, rb;
    uint32_t hi = split_pack_hi(a, b, ra, rb);
    ((uint32_t*)g_B0)[idx] = hi;
    ((uint32_t*)g_B1)[idx] = pack_bf16(ra, rb);
    if (k2 == 0) g_bias[n] = net ? bb[col] : ba[col];
}

// ---------------- GEMM1 (mma.sync, cp.async 2-stage): H0h = A@B^T + bias -----
#define SM_BIAS   0
#define SM_STAGE0 1024
#define STG_A0    0
#define STG_A1    8192
#define STG_B0    16384
#define STG_B1    32768
#define STAGE_BYTES 49152
#define GEMM1_SMEM (SM_STAGE0 + 2 * STAGE_BYTES)   // 99328 bytes

__device__ __forceinline__ void load_stage(uint32_t stage_base, int mbase, int nbase,
                                           int k0, int tid) {
#pragma unroll
    for (int p = 0; p < 2; p++) {
        uint32_t off = (uint32_t)(tid + p * 256) * 16;
        int row = off >> 7, inner = off & 127;
        int grow = mbase + row;
        int ok = (grow < NN) ? 16 : 0;
        int gr = (grow < NN) ? grow : (NN - 1);
        uint32_t sw = SMEM_SWIZZLE_128B(off);
        cp_async16(stage_base + STG_A0 + sw,
                   (const char*)g_A0 + ((size_t)gr * KPAD + k0) * 2 + inner, ok);
        cp_async16(stage_base + STG_A1 + sw,
                   (const char*)g_A1 + ((size_t)gr * KPAD + k0) * 2 + inner, ok);
    }
#pragma unroll
    for (int p = 0; p < 4; p++) {
        uint32_t off = (uint32_t)(tid + p * 256) * 16;
        int row = off >> 7, inner = off & 127;
        int nrow = nbase + row;
        uint32_t sw = SMEM_SWIZZLE_128B(off);
        cp_async16(stage_base + STG_B0 + sw,
                   (const char*)g_B0 + ((size_t)nrow * KPAD + k0) * 2 + inner, 16);
        cp_async16(stage_base + STG_B1 + sw,
                   (const char*)g_B1 + ((size_t)nrow * KPAD + k0) * 2 + inner, 16);
    }
}

__device__ __forceinline__ uint32_t addrA(uint32_t base, int m_local, int k0, int lane) {
    int mat = lane >> 3, r = lane & 7;
    int m = m_local + r + (mat & 1) * 8;
    int k = k0 + (mat >> 1) * 8;
    return base + (uint32_t)(m * 128 + (((k >> 3) ^ (m & 7)) << 4));
}
__device__ __forceinline__ uint32_t addrB(uint32_t base, int n_local, int k0, int lane) {
    int mat = lane >> 3, r = lane & 7;
    int n = n_local + r + ((mat >> 1) & 1) * 8;
    int k = k0 + (mat & 1) * 8;
    return base + (uint32_t)(n * 128 + (((k >> 3) ^ (n & 7)) << 4));
}

__global__ __launch_bounds__(256, 2)
void gemm1_mma_kernel() {
    extern __shared__ char smem[];
    uint32_t sb = smem_u32(smem);
    int tid  = threadIdx.x;
    int lane = tid & 31, wid = tid >> 5;
    int warp_m = wid & 1;
    int warp_n = wid >> 1;
    int nbase = blockIdx.x * 128;
    int mbase = blockIdx.y * 64;

    if (tid < 32)
        ((float4*)(smem + SM_BIAS))[tid] = ((const float4*)(g_bias + nbase))[tid];

    float acc[2][4][4];
#pragma unroll
    for (int i = 0; i < 2; i++)
#pragma unroll
        for (int j = 0; j < 4; j++)
#pragma unroll
            for (int q = 0; q < 4; q++) acc[i][j][q] = 0.f;

    uint32_t stg[2] = { sb + SM_STAGE0, sb + SM_STAGE0 + STAGE_BYTES };

    load_stage(stg[0], mbase, nbase, 0, tid);
    CP_COMMIT();
    load_stage(stg[1], mbase, nbase, 64, tid);
    CP_COMMIT();

    for (int kt = 0; kt < 8; kt++) {
        int cur = kt & 1;
        if (kt < 7) CP_WAIT1(); else CP_WAIT0();
        __syncthreads();

        uint32_t sa0 = stg[cur] + STG_A0, sa1 = stg[cur] + STG_A1;
        uint32_t sb0 = stg[cur] + STG_B0, sb1 = stg[cur] + STG_B1;
#pragma unroll
        for (int ks = 0; ks < 4; ks++) {
            int k0 = ks * 16;
            uint32_t a[2][4], b[2][4];
#pragma unroll
            for (int mf = 0; mf < 2; mf++)
                ldsm_x4(a[mf], addrA(sa0, warp_m * 32 + mf * 16, k0, lane));
#pragma unroll
            for (int g = 0; g < 2; g++)
                ldsm_x4(b[g], addrB(sb0, warp_n * 32 + g * 16, k0, lane));
#pragma unroll
            for (int mf = 0; mf < 2; mf++)
#pragma unroll
                for (int nf = 0; nf < 4; nf++)
                    mma16816(acc[mf][nf], a[mf],
                             b[nf >> 1][(nf & 1) * 2], b[nf >> 1][(nf & 1) * 2 + 1]);
#pragma unroll
            for (int mf = 0; mf < 2; mf++)
                ldsm_x4(a[mf], addrA(sa1, warp_m * 32 + mf * 16, k0, lane));
#pragma unroll
            for (int mf = 0; mf < 2; mf++)
#pragma unroll
                for (int nf = 0; nf < 4; nf++)
                    mma16816(acc[mf][nf], a[mf],
                             b[nf >> 1][(nf & 1) * 2], b[nf >> 1][(nf & 1) * 2 + 1]);
#pragma unroll
            for (int mf = 0; mf < 2; mf++)
                ldsm_x4(a[mf], addrA(sa0, warp_m * 32 + mf * 16, k0, lane));
#pragma unroll
            for (int g = 0; g < 2; g++)
                ldsm_x4(b[g], addrB(sb1, warp_n * 32 + g * 16, k0, lane));
#pragma unroll
            for (int mf = 0; mf < 2; mf++)
#pragma unroll
                for (int nf = 0; nf < 4; nf++)
                    mma16816(acc[mf][nf], a[mf],
                             b[nf >> 1][(nf & 1) * 2], b[nf >> 1][(nf & 1) * 2 + 1]);
        }
        __syncthreads();
        if (kt + 2 < 8) {
            load_stage(stg[cur], mbase, nbase, (kt + 2) * 64, tid);
            CP_COMMIT();
        }
    }

    // epilogue: fp16 store (half the DRAM writes; SPMM reads fp16)
    const float* bs = (const float*)(smem + SM_BIAS);
#pragma unroll
    for (int mf = 0; mf < 2; mf++) {
#pragma unroll
        for (int nf = 0; nf < 4; nf++) {
            int ncol = warp_n * 32 + nf * 8 + (lane & 3) * 2;
            float bx = bs[ncol], by = bs[ncol + 1];
            int r0 = mbase + warp_m * 32 + mf * 16 + (lane >> 2);
            if (r0 < NN) {
                __half2 v = __floats2half2_rn(acc[mf][nf][0] + bx,
                                              acc[mf][nf][1] + by);
                *(__half2*)(g_H0h + (size_t)r0 * HID2 + nbase + ncol) = v;
            }
            int r1 = r0 + 8;
            if (r1 < NN) {
                __half2 v = __floats2half2_rn(acc[mf][nf][2] + bx,
                                              acc[mf][nf][3] + by);
                *(__half2*)(g_H0h + (size_t)r1 * HID2 + nbase + ncol) = v;
            }
        }
    }
}

// ---------------- SPMM1 + ReLU + GEMM2 fused (fp16 gather) -------------------
// block per row: gather fp16 (8B/thread/edge) -> fp32 acc -> relu -> dense 20
__global__ __launch_bounds__(128)
void spmm1_fused_kernel(const float* __restrict__ W2a, const float* __restrict__ b2a,
                        const float* __restrict__ W2b, const float* __restrict__ b2b) {
    __shared__ __align__(16) float sh[HID2];
    int r = blockIdx.x;
    int t = threadIdx.x;
    const __half* H0b = g_H0h + (size_t)t * 4;   // this thread's 4 columns
    float4 acc = make_float4(0.f, 0.f, 0.f, 0.f);
    int beg = g_rowptr[r], end = g_rowptr[r + 1];
    int e = beg;
    for (; e + 3 < end; e += 4) {
        int c0 = __ldg(&g_cols[e]),     c1 = __ldg(&g_cols[e + 1]);
        int c2 = __ldg(&g_cols[e + 2]), c3 = __ldg(&g_cols[e + 3]);
        float w0 = __ldg(&g_w[e]),     w1 = __ldg(&g_w[e + 1]);
        float w2 = __ldg(&g_w[e + 2]), w3 = __ldg(&g_w[e + 3]);
        uint2 u0 = *(const uint2*)(H0b + (size_t)c0 * HID2);
        uint2 u1 = *(const uint2*)(H0b + (size_t)c1 * HID2);
        uint2 u2 = *(const uint2*)(H0b + (size_t)c2 * HID2);
        uint2 u3 = *(const uint2*)(H0b + (size_t)c3 * HID2);
        float2 a0 = __half22float2(*(__half2*)&u0.x), b0 = __half22float2(*(__half2*)&u0.y);
        float2 a1 = __half22float2(*(__half2*)&u1.x), b1 = __half22float2(*(__half2*)&u1.y);
        float2 a2 = __half22float2(*(__half2*)&u2.x), b2 = __half22float2(*(__half2*)&u2.y);
        float2 a3 = __half22float2(*(__half2*)&u3.x), b3 = __half22float2(*(__half2*)&u3.y);
        acc.x += w0 * a0.x + w1 * a1.x + w2 * a2.x + w3 * a3.x;
        acc.y += w0 * a0.y + w1 * a1.y + w2 * a2.y + w3 * a3.y;
        acc.z += w0 * b0.x + w1 * b1.x + w2 * b2.x + w3 * b3.x;
        acc.w += w0 * b0.y + w1 * b1.y + w2 * b2.y + w3 * b3.y;
    }
    for (; e < end; e++) {
        int c0 = __ldg(&g_cols[e]);
        float w0 = __ldg(&g_w[e]);
        uint2 u0 = *(const uint2*)(H0b + (size_t)c0 * HID2);
        float2 a0 = __half22float2(*(__half2*)&u0.x), b0 = __half22float2(*(__half2*)&u0.y);
        acc.x += w0 * a0.x; acc.y += w0 * a0.y;
        acc.z += w0 * b0.x; acc.w += w0 * b0.y;
    }
    float4 h;
    h.x = fmaxf(acc.x, 0.f); h.y = fmaxf(acc.y, 0.f);
    h.z = fmaxf(acc.z, 0.f); h.w = fmaxf(acc.w, 0.f);
    ((float4*)sh)[t] = h;
    __syncthreads();

    // dense layer: 20 outputs over 4 warps (5 each)
    int warp = t >> 5, lane = t & 31;
#pragma unroll
    for (int j = 0; j < 5; j++) {
        int c   = warp * 5 + j;          // 0..19
        int net = (c >= NC) ? 1 : 0;
        int cc  = c - net * NC;
        const float* W = net ? W2b : W2a;
        const float* hh = sh + net * NH;
        float s = 0.f;
#pragma unroll
        for (int i = 0; i < NH / 32; i++) {
            int k = lane + i * 32;
            s += hh[k] * __ldg(&W[(size_t)k * NC + cc]);
        }
#pragma unroll
        for (int o = 16; o; o >>= 1) s += __shfl_xor_sync(0xFFFFFFFFu, s, o);
        if (lane == 0)
            g_H2[(size_t)r * 2 * NC + c] =
                s + (net ? __ldg(&b2b[cc]) : __ldg(&b2a[cc]));
    }
}

// ---------------- SPMM2 -> output: warp per row, 20 active lanes -------------
__global__ __launch_bounds__(256)
void spmm2_kernel(float* __restrict__ out) {
    int gid  = blockIdx.x * blockDim.x + threadIdx.x;
    int warp = gid >> 5;
    int lane = threadIdx.x & 31;
    if (warp >= NN) return;
    int beg = g_rowptr[warp], end = g_rowptr[warp + 1];
    float acc = 0.f;
    for (int e = beg; e < end; e++) {
        int c = __ldg(&g_cols[e]);
        float w = __ldg(&g_w[e]);
        if (lane < 2 * NC) acc += w * g_H2[(size_t)c * 2 * NC + lane];
    }
    if (lane < NC)
        out[(size_t)warp * NC + lane] = acc;
    else if (lane < 2 * NC)
        out[(size_t)NN * NC + (size_t)warp * NC + (lane - NC)] = acc;
}

// ---------------- launch -----------------------------------------------------
extern "C" void kernel_launch(void* const* d_in, const int* in_sizes, int n_in,
                              void* d_out, int out_size) {
    const float* x    = (const float*)d_in[0];
    const void*  ei   = d_in[1];
    const float* ew   = (const float*)d_in[2];
    const float* W1a  = (const float*)d_in[3];
    const float* b1a  = (const float*)d_in[4];
    const float* W2a  = (const float*)d_in[5];
    const float* b2a  = (const float*)d_in[6];
    const float* W1b  = (const float*)d_in[7];
    const float* b1b  = (const float*)d_in[8];
    const float* W2b  = (const float*)d_in[9];
    const float* b2b  = (const float*)d_in[10];
    float* out = (float*)d_out;

    cudaFuncSetAttribute(gemm1_mma_kernel,
                         cudaFuncAttributeMaxDynamicSharedMemorySize, GEMM1_SMEM);

    // order keeps gemm1 in the profiled 4th launch slot
    convertA_kernel<<<(NN * (KPAD / 2) + 255) / 256, 256>>>(x);
    convertB_kernel<<<(HID2 * (KPAD / 2) + 255) / 256, 256>>>(W1a, b1a, W1b, b1b);
    zero_kernel<<<(NN + 255) / 256, 256>>>();

    dim3 g1(HID2 / 128, (NN + 63) / 64);
    gemm1_mma_kernel<<<g1, 256, GEMM1_SMEM>>>();

    // CSR build (dtype-safe, graph-capturable)
    detect_kernel<<<(NE + 255) / 256, 256>>>((const long long*)ei);
    count_kernel<<<(NE + 255) / 256, 256>>>(ei);
    scan1_kernel<<<SCAN_NB, 256>>>();
    scan2_kernel<<<1, 256>>>();
    scan3_kernel<<<(NN + 255) / 256, 256>>>();
    scatter_kernel<<<(NE + 255) / 256, 256>>>(ei, ew);

    // propagate + relu + layer-2 linear (fused, fp16 gather)
    spmm1_fused_kernel<<<NN, 128>>>(W2a, b2a, W2b, b2b);

    // propagate -> outputs
    spmm2_kernel<<<(NN * 32 + 255) / 256, 256>>>(out);
}